// round 2
// baseline (speedup 1.0000x reference)
#include <cuda_runtime.h>
#include <math.h>

// Problem constants
#define BATCH   2
#define TSEQ    2048
#define CDIM    1024
#define HEADS   16
#define HD      64
#define BT      (BATCH * TSEQ)          // 4096 rows
#define QKVDIM  (3 * CDIM)              // 3072

// Scratch (allocation-free rule: __device__ globals)
__device__ float g_qkv[(size_t)BT * QKVDIM];   // [4096, 3072]
__device__ float g_ao [(size_t)BT * CDIM];     // [4096, 1024]

// ---------------------------------------------------------------------------
// GEMM: C[M,N] = A[M,K] @ B[N,K]^T   (both row-major, K contiguous)
// 128x128 block tile, BK=16, 256 threads, 8x8 per-thread microtile.
// ---------------------------------------------------------------------------
#define GBM 128
#define GBN 128
#define GBK 16

__global__ __launch_bounds__(256) void sgemm_nt(
    const float* __restrict__ A, const float* __restrict__ B,
    float* __restrict__ C, int M, int N, int K)
{
    __shared__ float As[GBK][GBM];
    __shared__ float Bs[GBK][GBN];

    const int tid = threadIdx.x;
    const int tx = tid & 15;           // 0..15
    const int ty = tid >> 4;           // 0..15
    const int m0 = blockIdx.y * GBM;
    const int n0 = blockIdx.x * GBN;

    float acc[8][8];
#pragma unroll
    for (int i = 0; i < 8; i++)
#pragma unroll
        for (int j = 0; j < 8; j++) acc[i][j] = 0.0f;

    for (int k0 = 0; k0 < K; k0 += GBK) {
        // Load tiles: 128 rows x 16 cols each = 512 float4 per matrix
#pragma unroll
        for (int e = tid; e < (GBM * GBK) / 4; e += 256) {
            int row = e >> 2;
            int c4  = (e & 3) * 4;
            float4 va = *(const float4*)(A + (size_t)(m0 + row) * K + k0 + c4);
            As[c4 + 0][row] = va.x; As[c4 + 1][row] = va.y;
            As[c4 + 2][row] = va.z; As[c4 + 3][row] = va.w;
            float4 vb = *(const float4*)(B + (size_t)(n0 + row) * K + k0 + c4);
            Bs[c4 + 0][row] = vb.x; Bs[c4 + 1][row] = vb.y;
            Bs[c4 + 2][row] = vb.z; Bs[c4 + 3][row] = vb.w;
        }
        __syncthreads();

#pragma unroll
        for (int kk = 0; kk < GBK; kk++) {
            float4 a0 = *(const float4*)&As[kk][ty * 8];
            float4 a1 = *(const float4*)&As[kk][ty * 8 + 4];
            float4 b0 = *(const float4*)&Bs[kk][tx * 8];
            float4 b1 = *(const float4*)&Bs[kk][tx * 8 + 4];
            float a[8] = {a0.x, a0.y, a0.z, a0.w, a1.x, a1.y, a1.z, a1.w};
            float b[8] = {b0.x, b0.y, b0.z, b0.w, b1.x, b1.y, b1.z, b1.w};
#pragma unroll
            for (int i = 0; i < 8; i++)
#pragma unroll
                for (int j = 0; j < 8; j++)
                    acc[i][j] = fmaf(a[i], b[j], acc[i][j]);
        }
        __syncthreads();
    }

#pragma unroll
    for (int i = 0; i < 8; i++) {
        float* crow = C + (size_t)(m0 + ty * 8 + i) * N + n0 + tx * 8;
        float4 o0 = make_float4(acc[i][0], acc[i][1], acc[i][2], acc[i][3]);
        float4 o1 = make_float4(acc[i][4], acc[i][5], acc[i][6], acc[i][7]);
        *(float4*)(crow)     = o0;
        *(float4*)(crow + 4) = o1;
    }
}

// ---------------------------------------------------------------------------
// RoPE in-place on q and k thirds of g_qkv. Interleaved pairs (2i, 2i+1).
// ---------------------------------------------------------------------------
__global__ __launch_bounds__(256) void rope_kernel(
    float* __restrict__ qkv, const float* __restrict__ cs,
    const float* __restrict__ sn)
{
    const int total = BT * HEADS * (HD / 2);   // 2,097,152
    for (int idx = blockIdx.x * blockDim.x + threadIdx.x; idx < total;
         idx += gridDim.x * blockDim.x) {
        int i   = idx & 31;
        int h   = (idx >> 5) & 15;
        int row = idx >> 9;
        int t   = row & (TSEQ - 1);
        float c = cs[t * 32 + i];
        float s = sn[t * 32 + i];
        float* q = qkv + (size_t)row * QKVDIM + h * HD + 2 * i;
        float2 qv = *(float2*)q;
        *(float2*)q = make_float2(qv.x * c - qv.y * s, qv.x * s + qv.y * c);
        float* k = q + CDIM;
        float2 kv = *(float2*)k;
        *(float2*)k = make_float2(kv.x * c - kv.y * s, kv.x * s + kv.y * c);
    }
}

// ---------------------------------------------------------------------------
// Causal flash attention, fp32. 64x64 tiles, D=64, 256 threads.
// Thread (tx,ty) owns 4 score rows (ty*4..) x 4 cols (tx*4..) and the same
// 4x4 footprint of the (row, d) output accumulator.
// Row reductions via shfl_xor over lane bits [0:4) == tx.
// ---------------------------------------------------------------------------
#define AM 64
#define AN 64
#define PSTR 68   // padded smem stride (bank-conflict-free, float4-aligned)

__global__ __launch_bounds__(256) void attn_kernel(
    const float* __restrict__ qkv, float* __restrict__ ao)
{
    extern __shared__ float sm[];
    float* Qs = sm;                       // [64][68]
    float* Ks = Qs + AM * PSTR;           // [64][68]
    float* Ps = Ks + AN * PSTR;           // [64][68]
    float* Vs = Ps + AM * PSTR;           // [64][64]

    const int m0 = blockIdx.x * AM;
    const int h  = blockIdx.y;
    const int b  = blockIdx.z;
    const int tid = threadIdx.x;
    const int tx = tid & 15, ty = tid >> 4;
    const int r0 = ty * 4, c0 = tx * 4;

    const float* qbase = qkv + (size_t)b * TSEQ * QKVDIM + h * HD;

    // Load Q tile (64 rows x 16 float4)
    for (int e = tid; e < AM * 16; e += 256) {
        int r = e >> 4, c4 = (e & 15) * 4;
        float4 v = *(const float4*)(qbase + (size_t)(m0 + r) * QKVDIM + c4);
        *(float4*)(Qs + r * PSTR + c4) = v;
    }

    float acc[4][4];
    float mi[4], li[4];
#pragma unroll
    for (int i = 0; i < 4; i++) {
        mi[i] = -1e30f; li[i] = 0.0f;
#pragma unroll
        for (int j = 0; j < 4; j++) acc[i][j] = 0.0f;
    }

    const float scale = 0.125f;  // 1/sqrt(64)

    for (int n0 = 0; n0 <= m0; n0 += AN) {
        __syncthreads();   // protects Qs on iter0; Ks/Vs/Ps reuse afterwards
        const float* kbase = qkv + ((size_t)b * TSEQ + n0) * QKVDIM + CDIM + h * HD;
        const float* vbase = kbase + CDIM;
        for (int e = tid; e < AN * 16; e += 256) {
            int r = e >> 4, c4 = (e & 15) * 4;
            *(float4*)(Ks + r * PSTR + c4) =
                *(const float4*)(kbase + (size_t)r * QKVDIM + c4);
            *(float4*)(Vs + r * HD + c4) =
                *(const float4*)(vbase + (size_t)r * QKVDIM + c4);
        }
        __syncthreads();

        // Scores s[4][4] = Q[r0+i,:] . K[c0+j,:]
        float s[4][4];
#pragma unroll
        for (int i = 0; i < 4; i++)
#pragma unroll
            for (int j = 0; j < 4; j++) s[i][j] = 0.0f;

#pragma unroll
        for (int d = 0; d < HD; d += 4) {
            float4 a[4], kb[4];
#pragma unroll
            for (int i = 0; i < 4; i++)
                a[i] = *(const float4*)(Qs + (r0 + i) * PSTR + d);
#pragma unroll
            for (int j = 0; j < 4; j++)
                kb[j] = *(const float4*)(Ks + (c0 + j) * PSTR + d);
#pragma unroll
            for (int i = 0; i < 4; i++)
#pragma unroll
                for (int j = 0; j < 4; j++) {
                    s[i][j] = fmaf(a[i].x, kb[j].x, s[i][j]);
                    s[i][j] = fmaf(a[i].y, kb[j].y, s[i][j]);
                    s[i][j] = fmaf(a[i].z, kb[j].z, s[i][j]);
                    s[i][j] = fmaf(a[i].w, kb[j].w, s[i][j]);
                }
        }

        // scale + causal mask (only diagonal tile needs it)
        const bool diag = (n0 == m0);
#pragma unroll
        for (int i = 0; i < 4; i++)
#pragma unroll
            for (int j = 0; j < 4; j++) {
                s[i][j] *= scale;
                if (diag && (n0 + c0 + j) > (m0 + r0 + i)) s[i][j] = -1e30f;
            }

        // Online softmax update
#pragma unroll
        for (int i = 0; i < 4; i++) {
            float mloc = fmaxf(fmaxf(s[i][0], s[i][1]), fmaxf(s[i][2], s[i][3]));
#pragma unroll
            for (int o = 8; o >= 1; o >>= 1)
                mloc = fmaxf(mloc, __shfl_xor_sync(0xffffffffu, mloc, o));
            float newm = fmaxf(mi[i], mloc);
            float alpha = __expf(mi[i] - newm);
            float p0 = __expf(s[i][0] - newm);
            float p1 = __expf(s[i][1] - newm);
            float p2 = __expf(s[i][2] - newm);
            float p3 = __expf(s[i][3] - newm);
            float rs = p0 + p1 + p2 + p3;
#pragma unroll
            for (int o = 8; o >= 1; o >>= 1)
                rs += __shfl_xor_sync(0xffffffffu, rs, o);
            li[i] = li[i] * alpha + rs;
            mi[i] = newm;
#pragma unroll
            for (int j = 0; j < 4; j++) acc[i][j] *= alpha;
            *(float4*)(Ps + (r0 + i) * PSTR + c0) = make_float4(p0, p1, p2, p3);
        }
        __syncthreads();

        // acc += P[r0+i, :] @ V[:, c0+j]
#pragma unroll 4
        for (int kk = 0; kk < AN; kk++) {
            float a0 = Ps[(r0 + 0) * PSTR + kk];
            float a1 = Ps[(r0 + 1) * PSTR + kk];
            float a2 = Ps[(r0 + 2) * PSTR + kk];
            float a3 = Ps[(r0 + 3) * PSTR + kk];
            float4 bv = *(const float4*)(Vs + kk * HD + c0);
            acc[0][0] = fmaf(a0, bv.x, acc[0][0]); acc[0][1] = fmaf(a0, bv.y, acc[0][1]);
            acc[0][2] = fmaf(a0, bv.z, acc[0][2]); acc[0][3] = fmaf(a0, bv.w, acc[0][3]);
            acc[1][0] = fmaf(a1, bv.x, acc[1][0]); acc[1][1] = fmaf(a1, bv.y, acc[1][1]);
            acc[1][2] = fmaf(a1, bv.z, acc[1][2]); acc[1][3] = fmaf(a1, bv.w, acc[1][3]);
            acc[2][0] = fmaf(a2, bv.x, acc[2][0]); acc[2][1] = fmaf(a2, bv.y, acc[2][1]);
            acc[2][2] = fmaf(a2, bv.z, acc[2][2]); acc[2][3] = fmaf(a2, bv.w, acc[2][3]);
            acc[3][0] = fmaf(a3, bv.x, acc[3][0]); acc[3][1] = fmaf(a3, bv.y, acc[3][1]);
            acc[3][2] = fmaf(a3, bv.z, acc[3][2]); acc[3][3] = fmaf(a3, bv.w, acc[3][3]);
        }
    }

    // Normalize and write out: ao[(b*T + row), h*64 + d]
#pragma unroll
    for (int i = 0; i < 4; i++) {
        float inv = 1.0f / li[i];
        float* orow = ao + ((size_t)b * TSEQ + m0 + r0 + i) * CDIM + h * HD + c0;
        *(float4*)orow = make_float4(acc[i][0] * inv, acc[i][1] * inv,
                                     acc[i][2] * inv, acc[i][3] * inv);
    }
}

// ---------------------------------------------------------------------------
// Host launcher
// ---------------------------------------------------------------------------
extern "C" void kernel_launch(void* const* d_in, const int* in_sizes, int n_in,
                              void* d_out, int out_size)
{
    const float* x       = (const float*)d_in[0];  // [2,2048,1024]
    const float* f_cos   = (const float*)d_in[1];  // [2048,32]
    const float* f_sin   = (const float*)d_in[2];  // [2048,32]
    const float* qkv_w   = (const float*)d_in[3];  // [3072,1024]
    const float* proj_w  = (const float*)d_in[4];  // [1024,1024]
    float* out = (float*)d_out;

    float *qkv_ptr, *ao_ptr;
    cudaGetSymbolAddress((void**)&qkv_ptr, g_qkv);
    cudaGetSymbolAddress((void**)&ao_ptr, g_ao);

    // 1) QKV projection: [4096,3072] = x @ qkv_w^T
    {
        dim3 grid(QKVDIM / GBN, BT / GBM);
        sgemm_nt<<<grid, 256>>>(x, qkv_w, qkv_ptr, BT, QKVDIM, CDIM);
    }

    // 2) RoPE in place on q,k thirds
    rope_kernel<<<2048, 256>>>(qkv_ptr, f_cos, f_sin);

    // 3) Causal attention
    {
        const int smem = (3 * AM * PSTR + AN * HD) * (int)sizeof(float); // ~68.6 KB
        cudaFuncSetAttribute(attn_kernel,
                             cudaFuncAttributeMaxDynamicSharedMemorySize, smem);
        dim3 grid(TSEQ / AM, HEADS, BATCH);
        attn_kernel<<<grid, 256, smem>>>(qkv_ptr, ao_ptr);
    }

    // 4) Output projection: [4096,1024] = ao @ proj_w^T
    {
        dim3 grid(CDIM / GBN, BT / GBM);
        sgemm_nt<<<grid, 256>>>(ao_ptr, proj_w, out, BT, CDIM, CDIM);
    }
}